// round 5
// baseline (speedup 1.0000x reference)
#include <cuda_runtime.h>

// FasterTensorProduct — fused single kernel.
// Block = one (b, n2): compute Y[k][c] = (x_row @ A_c)[k] into smem, then
// out[b,n1,n2,k] = dot4(sh[b,n1], Y[k]) for all 128 n1.
//
// in_ (4,1,128,272) f32, sh (4,128,1,4) f32, weight (13568,) f32.
// out (4,128,128,272) f32.

#define IN_DIM 272
#define NB     4
#define NN     128

#define W0E_OFF 0      // 96 x 64
#define W1O_OFF 6144   // 128 x 32
#define W1E_OFF 10240  // 80 x 32
#define W0O_OFF 12800  // 48 x 16

// Partial layout (floats): A[2][64][4] | B[2][32][7] | C[2][32][7] | D[2][16][4]
#define PA 0
#define PB 512
#define PC 960
#define PD 1408
#define PTOT 1536

#define NTHREADS 544   // 8 n1-groups x 68 kv

__global__ __launch_bounds__(NTHREADS, 3) void tp_fused(const float* __restrict__ in_,
                                                        const float* __restrict__ sh,
                                                        const float* __restrict__ w,
                                                        float* __restrict__ out)
{
    __shared__ float  sx[IN_DIM];
    __shared__ float4 ssh[NN];
    __shared__ float  part[PTOT];
    __shared__ float4 sY[IN_DIM];

    const int t  = threadIdx.x;
    const int b  = blockIdx.x >> 7;
    const int n2 = blockIdx.x & 127;

    // ---- phase 0: stage x row and sh tile ----
    if (t < IN_DIM)
        sx[t] = in_[(b * NN + n2) * IN_DIM + t];
    else if (t < IN_DIM + NN)
        ssh[t - IN_DIM] = reinterpret_cast<const float4*>(sh)[b * NN + (t - IN_DIM)];
    __syncthreads();

    // ---- phase 1: Y = x @ A_c, two-half split reduction ----
    {
        const int half = (t >= 272) ? 1 : 0;
        const int u    = t - 272 * half;

        if (u < 64) {
            // segment A partials: o = u
            const int o = u;
            const int j0 = half * 32, k0 = half * 16;
            float a0 = 0.f, a1[3] = {};
            #pragma unroll 8
            for (int j = j0; j < j0 + 32; j++)
                a0 += sx[j] * w[W0E_OFF + j * 64 + o];
            #pragma unroll 4
            for (int k = k0; k < k0 + 16; k++) {
                const float wv = w[W0E_OFF + (64 + k) * 64 + o];
                #pragma unroll
                for (int d = 0; d < 3; d++) a1[d] += sx[64 + 3 * k + d] * wv;
            }
            float* p = &part[PA + half * 256 + o * 4];
            p[0] = a0; p[1] = a1[0]; p[2] = a1[1]; p[3] = a1[2];
        }
        else if (u < 96) {
            // segment B partials: o = u-64
            const int o = u - 64;
            const int j0 = half * 32, k0 = half * 16;
            float b0 = 0.f, b1[3] = {}, b2[3] = {};
            #pragma unroll 8
            for (int j = j0; j < j0 + 32; j++)
                b0 += sx[j] * w[W1O_OFF + j * 32 + o];
            #pragma unroll 4
            for (int k = k0; k < k0 + 16; k++) {
                const float wv = w[W1O_OFF + (64 + k) * 32 + o];
                #pragma unroll
                for (int d = 0; d < 3; d++) b1[d] += sx[64 + 3 * k + d] * wv;
            }
            #pragma unroll 4
            for (int k = k0; k < k0 + 16; k++) {
                const float wv = w[W1O_OFF + (96 + k) * 32 + o];
                #pragma unroll
                for (int e = 0; e < 3; e++) b2[e] += sx[160 + 3 * k + e] * wv;
            }
            float* p = &part[PB + half * 224 + o * 7];
            p[0] = b0;
            p[1] = b1[0]; p[2] = b1[1]; p[3] = b1[2];
            p[4] = b2[0]; p[5] = b2[1]; p[6] = b2[2];
        }
        else if (u < 128) {
            // segment C partials: o = u-96
            const int o = u - 96;
            const int k0 = half * 16, j0 = half * 8;
            float c0[3] = {}, c1[3] = {}, c2 = 0.f;
            #pragma unroll 4
            for (int k = k0; k < k0 + 16; k++) {
                const float wv = w[W1E_OFF + k * 32 + o];
                #pragma unroll
                for (int e = 0; e < 3; e++) c0[e] += sx[64 + 3 * k + e] * wv;
            }
            #pragma unroll 4
            for (int k = k0; k < k0 + 16; k++) {
                const float wv = w[W1E_OFF + (32 + k) * 32 + o];
                #pragma unroll
                for (int d = 0; d < 3; d++) c1[d] += sx[160 + 3 * k + d] * wv;
            }
            #pragma unroll 8
            for (int j = j0; j < j0 + 8; j++)
                c2 += sx[256 + j] * w[W1E_OFF + (64 + j) * 32 + o];
            float* p = &part[PC + half * 224 + o * 7];
            p[0] = c2;
            p[1] = c0[0]; p[2] = c0[1]; p[3] = c0[2];
            p[4] = c1[0]; p[5] = c1[1]; p[6] = c1[2];
        }
        else if (u < 144) {
            // segment D partials: o = u-128
            const int o = u - 128;
            const int k0 = half * 16, j0 = half * 8;
            float d0[3] = {}, d1 = 0.f;
            #pragma unroll 4
            for (int k = k0; k < k0 + 16; k++) {
                const float wv = w[W0O_OFF + k * 16 + o];
                #pragma unroll
                for (int d = 0; d < 3; d++) d0[d] += sx[160 + 3 * k + d] * wv;
            }
            #pragma unroll 8
            for (int j = j0; j < j0 + 8; j++)
                d1 += sx[256 + j] * w[W0O_OFF + (32 + j) * 16 + o];
            float* p = &part[PD + half * 64 + o * 4];
            p[0] = d1; p[1] = d0[0]; p[2] = d0[1]; p[3] = d0[2];
        }
        __syncthreads();

        // combine halves (half 0 only)
        if (!half) {
            if (u < 64) {
                const int o = u;
                const float* p0 = &part[PA + o * 4];
                const float* p1 = &part[PA + 256 + o * 4];
                const float s  = 0.10206207262f;   // 1/sqrt(96)
                const float s3 = 0.05892556510f;   // 1/sqrt(96*3)
                sY[o] = make_float4(s  * (p0[0] + p1[0]), s3 * (p0[1] + p1[1]),
                                    s3 * (p0[2] + p1[2]), s3 * (p0[3] + p1[3]));
            }
            else if (u < 96) {
                const int o = u - 64;
                const float* p0 = &part[PB + o * 7];
                const float* p1 = &part[PB + 224 + o * 7];
                const float b0 = p0[0] + p1[0];
                float b1[3], b2[3];
                #pragma unroll
                for (int d = 0; d < 3; d++) {
                    b1[d] = p0[1 + d] + p1[1 + d];
                    b2[d] = p0[4 + d] + p1[4 + d];
                }
                const float s   = 0.08838834765f;  // 1/sqrt(128)
                const float si2 = 0.0625f;         // 1/sqrt(256)
                #pragma unroll
                for (int c = 0; c < 3; c++) {
                    float v[4];
                    v[0]               =  s   * b1[c];
                    v[1 + c]           =  s   * b0;
                    v[1 + (c + 2) % 3] =  si2 * b2[(c + 1) % 3];
                    v[1 + (c + 1) % 3] = -si2 * b2[(c + 2) % 3];
                    sY[64 + 3 * o + c] = make_float4(v[0], v[1], v[2], v[3]);
                }
            }
            else if (u < 128) {
                const int o = u - 96;
                const float* p0 = &part[PC + o * 7];
                const float* p1 = &part[PC + 224 + o * 7];
                const float c2 = p0[0] + p1[0];
                float c0[3], c1[3];
                #pragma unroll
                for (int d = 0; d < 3; d++) {
                    c0[d] = p0[1 + d] + p1[1 + d];
                    c1[d] = p0[4 + d] + p1[4 + d];
                }
                const float s   = 0.11180339887f;  // 1/sqrt(80)
                const float si2 = 0.07905694150f;  // 1/sqrt(160)
                #pragma unroll
                for (int c = 0; c < 3; c++) {
                    float v[4];
                    v[0]               =  s   * c1[c];
                    v[1 + c]           =  s   * c2;
                    v[1 + (c + 2) % 3] =  si2 * c0[(c + 1) % 3];
                    v[1 + (c + 1) % 3] = -si2 * c0[(c + 2) % 3];
                    sY[160 + 3 * o + c] = make_float4(v[0], v[1], v[2], v[3]);
                }
            }
            else if (u < 144) {
                const int o = u - 128;
                const float* p0 = &part[PD + o * 4];
                const float* p1 = &part[PD + 64 + o * 4];
                const float s  = 0.14433756730f;   // 1/sqrt(48)
                const float s3 = 0.08333333333f;   // 1/12
                sY[256 + o] = make_float4(s  * (p0[0] + p1[0]), s3 * (p0[1] + p1[1]),
                                          s3 * (p0[2] + p1[2]), s3 * (p0[3] + p1[3]));
            }
        }
    }
    __syncthreads();

    // ---- phase 2: out[b,n1,n2,:] = dot4(sh[b,n1], Y) ----
    const int kv  = t % 68;       // float4 index within 272
    const int n1l = t / 68;       // 0..7

    const float4 y0 = sY[kv * 4 + 0];
    const float4 y1 = sY[kv * 4 + 1];
    const float4 y2 = sY[kv * 4 + 2];
    const float4 y3 = sY[kv * 4 + 3];

    float4* op = reinterpret_cast<float4*>(out)
               + ((size_t)(b * NN + n1l) * NN + n2) * (IN_DIM / 4) + kv;
    const size_t stride8 = (size_t)8 * NN * (IN_DIM / 4);  // 8 n1 rows of float4

    #pragma unroll
    for (int i = 0; i < 16; i++) {
        const float4 s = ssh[i * 8 + n1l];
        float4 o;
        o.x = s.x * y0.x + s.y * y0.y + s.z * y0.z + s.w * y0.w;
        o.y = s.x * y1.x + s.y * y1.y + s.z * y1.z + s.w * y1.w;
        o.z = s.x * y2.x + s.y * y2.y + s.z * y2.z + s.w * y2.w;
        o.w = s.x * y3.x + s.y * y3.y + s.z * y3.z + s.w * y3.w;
        op[i * stride8] = o;
    }
}

extern "C" void kernel_launch(void* const* d_in, const int* in_sizes, int n_in,
                              void* d_out, int out_size)
{
    const float* in_ = (const float*)d_in[0];   // (4,1,128,272)
    const float* sh  = (const float*)d_in[1];   // (4,128,1,4)
    const float* w   = (const float*)d_in[2];   // (13568,)
    float* out = (float*)d_out;

    tp_fused<<<NB * NN, NTHREADS>>>(in_, sh, w, out);
}

// round 8
// speedup vs baseline: 1.1719x; 1.1719x over previous
#include <cuda_runtime.h>

// FasterTensorProduct — bilinear factorization, two kernels.
// out[b,n1,n2,k] = sum_c sh[b,n1,c] * Y[b,n2][k][c],  Y = x @ A_c (weight-derived).

#define IN_DIM 272
#define NROW   512   // B*N
#define NB     4
#define NN     128

#define W0E_OFF 0      // 96 x 64
#define W1O_OFF 6144   // 128 x 32
#define W1E_OFF 10240  // 80 x 32
#define W0O_OFF 12800  // 48 x 16

// Y scratch: [row][k] float4 (c innermost). 512*272*16B = 2.23 MB (L2-resident).
__device__ float4 g_Y[NROW * IN_DIM];

// ---------------------------------------------------------------------------
// Stage 1: per input row, compute Y[k][c]. One row per block, 576 threads:
// four quarters (t/144) each reduce 1/4 of the contraction range (~25-FMA
// chains), then combine through shared memory.
// ---------------------------------------------------------------------------
// Partial layout (floats): A[4][64][4] | B[4][32][7] | C[4][32][7] | D[4][16][4]
#define PA 0
#define PB 1024
#define PC 1920
#define PD 2816
#define PTOT 3072

__global__ __launch_bounds__(576) void tp_stage1(const float* __restrict__ in_,
                                                 const float* __restrict__ w)
{
    __shared__ float sx[IN_DIM];
    __shared__ float part[PTOT];
    const int r0 = blockIdx.x;
    const int t  = threadIdx.x;

    if (t < IN_DIM)
        sx[t] = in_[r0 * IN_DIM + t];
    __syncthreads();

    const int q = t / 144;      // quarter 0..3
    const int u = t - q * 144;  // 0..143

    if (u < 64) {
        // ---- segment A partials: o = u ----
        const int o = u;
        const int j0 = q * 16, k0 = q * 8;
        float a0 = 0.f, a1[3] = {};
        #pragma unroll
        for (int j = j0; j < j0 + 16; j++)
            a0 += sx[j] * w[W0E_OFF + j * 64 + o];
        #pragma unroll
        for (int k = k0; k < k0 + 8; k++) {
            const float wv = w[W0E_OFF + (64 + k) * 64 + o];
            #pragma unroll
            for (int d = 0; d < 3; d++) a1[d] += sx[64 + 3 * k + d] * wv;
        }
        float* p = &part[PA + q * 256 + o * 4];
        p[0] = a0; p[1] = a1[0]; p[2] = a1[1]; p[3] = a1[2];
    }
    else if (u < 96) {
        // ---- segment B partials: o = u-64 ----
        const int o = u - 64;
        const int j0 = q * 16, k0 = q * 8;
        float b0 = 0.f, b1[3] = {}, b2[3] = {};
        #pragma unroll
        for (int j = j0; j < j0 + 16; j++)
            b0 += sx[j] * w[W1O_OFF + j * 32 + o];
        #pragma unroll
        for (int k = k0; k < k0 + 8; k++) {
            const float wv = w[W1O_OFF + (64 + k) * 32 + o];
            #pragma unroll
            for (int d = 0; d < 3; d++) b1[d] += sx[64 + 3 * k + d] * wv;
        }
        #pragma unroll
        for (int k = k0; k < k0 + 8; k++) {
            const float wv = w[W1O_OFF + (96 + k) * 32 + o];
            #pragma unroll
            for (int e = 0; e < 3; e++) b2[e] += sx[160 + 3 * k + e] * wv;
        }
        float* p = &part[PB + q * 224 + o * 7];
        p[0] = b0;
        p[1] = b1[0]; p[2] = b1[1]; p[3] = b1[2];
        p[4] = b2[0]; p[5] = b2[1]; p[6] = b2[2];
    }
    else if (u < 128) {
        // ---- segment C partials: o = u-96 ----
        const int o = u - 96;
        const int k0 = q * 8, j0 = q * 4;
        float c0[3] = {}, c1[3] = {}, c2 = 0.f;
        #pragma unroll
        for (int k = k0; k < k0 + 8; k++) {
            const float wv = w[W1E_OFF + k * 32 + o];
            #pragma unroll
            for (int e = 0; e < 3; e++) c0[e] += sx[64 + 3 * k + e] * wv;
        }
        #pragma unroll
        for (int k = k0; k < k0 + 8; k++) {
            const float wv = w[W1E_OFF + (32 + k) * 32 + o];
            #pragma unroll
            for (int d = 0; d < 3; d++) c1[d] += sx[160 + 3 * k + d] * wv;
        }
        #pragma unroll
        for (int j = j0; j < j0 + 4; j++)
            c2 += sx[256 + j] * w[W1E_OFF + (64 + j) * 32 + o];
        float* p = &part[PC + q * 224 + o * 7];
        p[0] = c2;
        p[1] = c0[0]; p[2] = c0[1]; p[3] = c0[2];
        p[4] = c1[0]; p[5] = c1[1]; p[6] = c1[2];
    }
    else {
        // ---- segment D partials: o = u-128 ----
        const int o = u - 128;
        const int k0 = q * 8, j0 = q * 4;
        float d0[3] = {}, d1 = 0.f;
        #pragma unroll
        for (int k = k0; k < k0 + 8; k++) {
            const float wv = w[W0O_OFF + k * 16 + o];
            #pragma unroll
            for (int d = 0; d < 3; d++) d0[d] += sx[160 + 3 * k + d] * wv;
        }
        #pragma unroll
        for (int j = j0; j < j0 + 4; j++)
            d1 += sx[256 + j] * w[W0O_OFF + (32 + j) * 16 + o];
        float* p = &part[PD + q * 64 + o * 4];
        p[0] = d1; p[1] = d0[0]; p[2] = d0[1]; p[3] = d0[2];
    }
    __syncthreads();

    if (q) return;  // only quarter 0 combines

    if (u < 64) {
        const int o = u;
        float v[4] = {};
        #pragma unroll
        for (int qq = 0; qq < 4; qq++) {
            const float* p = &part[PA + qq * 256 + o * 4];
            #pragma unroll
            for (int d = 0; d < 4; d++) v[d] += p[d];
        }
        const float s  = 0.10206207262f;   // 1/sqrt(96)
        const float s3 = 0.05892556510f;   // 1/sqrt(96*3)
        g_Y[r0 * IN_DIM + o] = make_float4(s * v[0], s3 * v[1], s3 * v[2], s3 * v[3]);
    }
    else if (u < 96) {
        const int o = u - 64;
        float pz[7] = {};
        #pragma unroll
        for (int qq = 0; qq < 4; qq++) {
            const float* p = &part[PB + qq * 224 + o * 7];
            #pragma unroll
            for (int d = 0; d < 7; d++) pz[d] += p[d];
        }
        const float b0 = pz[0];
        const float* b1 = &pz[1];
        const float* b2 = &pz[4];
        const float s   = 0.08838834765f;  // 1/sqrt(128)
        const float si2 = 0.0625f;         // 1/sqrt(256)
        #pragma unroll
        for (int c = 0; c < 3; c++) {
            float v[4];
            v[0]               =  s   * b1[c];
            v[1 + c]           =  s   * b0;
            v[1 + (c + 2) % 3] =  si2 * b2[(c + 1) % 3];
            v[1 + (c + 1) % 3] = -si2 * b2[(c + 2) % 3];
            g_Y[r0 * IN_DIM + 64 + 3 * o + c] = make_float4(v[0], v[1], v[2], v[3]);
        }
    }
    else if (u < 128) {
        const int o = u - 96;
        float pz[7] = {};
        #pragma unroll
        for (int qq = 0; qq < 4; qq++) {
            const float* p = &part[PC + qq * 224 + o * 7];
            #pragma unroll
            for (int d = 0; d < 7; d++) pz[d] += p[d];
        }
        const float c2 = pz[0];
        const float* c0 = &pz[1];
        const float* c1 = &pz[4];
        const float s   = 0.11180339887f;  // 1/sqrt(80)
        const float si2 = 0.07905694150f;  // 1/sqrt(160)
        #pragma unroll
        for (int c = 0; c < 3; c++) {
            float v[4];
            v[0]               =  s   * c1[c];
            v[1 + c]           =  s   * c2;
            v[1 + (c + 2) % 3] =  si2 * c0[(c + 1) % 3];
            v[1 + (c + 1) % 3] = -si2 * c0[(c + 2) % 3];
            g_Y[r0 * IN_DIM + 160 + 3 * o + c] = make_float4(v[0], v[1], v[2], v[3]);
        }
    }
    else {
        const int o = u - 128;
        float v[4] = {};
        #pragma unroll
        for (int qq = 0; qq < 4; qq++) {
            const float* p = &part[PD + qq * 64 + o * 4];
            #pragma unroll
            for (int d = 0; d < 4; d++) v[d] += p[d];
        }
        const float s  = 0.14433756730f;   // 1/sqrt(48)
        const float s3 = 0.08333333333f;   // 1/12
        g_Y[r0 * IN_DIM + 256 + o] = make_float4(s * v[0], s3 * v[1], s3 * v[2], s3 * v[3]);
    }
}

// ---------------------------------------------------------------------------
// Stage 2 (unchanged from round 4, proven 14.9 us):
// out[b,n1,n2,k] = dot4(sh[b,n1], Y[b,n2][k]).
// 256-thread blocks, flat j = n2*68+kv addressing, sh tile in smem,
// 8 n1 per thread fully unrolled. Grid (34, 16, 4).
// ---------------------------------------------------------------------------
#define T1 8

__global__ __launch_bounds__(256, 6) void tp_stage2(const float* __restrict__ sh,
                                                    float* __restrict__ out)
{
    __shared__ float4 ssh[T1];
    const int tid = threadIdx.x;
    const int b   = blockIdx.z;
    const int n1b = blockIdx.y * T1;
    const int j   = blockIdx.x * 256 + tid;   // n2*68 + kv, 0..8703

    if (tid < T1)
        ssh[tid] = reinterpret_cast<const float4*>(sh)[b * NN + n1b + tid];
    __syncthreads();

    const int n2 = j / 68;
    const int kv = j - n2 * 68;

    const float4* Yp = &g_Y[(b * NN + n2) * IN_DIM + kv * 4];
    const float4 y0 = Yp[0], y1 = Yp[1], y2 = Yp[2], y3 = Yp[3];

    float4* op = reinterpret_cast<float4*>(out)
               + (size_t)(b * NN + n1b) * (NN * (IN_DIM / 4)) + j;
    const size_t stride = NN * (IN_DIM / 4);  // 8704 float4 per n1

    #pragma unroll
    for (int i = 0; i < T1; i++) {
        const float4 s = ssh[i];
        float4 o;
        o.x = s.x * y0.x + s.y * y0.y + s.z * y0.z + s.w * y0.w;
        o.y = s.x * y1.x + s.y * y1.y + s.z * y1.z + s.w * y1.w;
        o.z = s.x * y2.x + s.y * y2.y + s.z * y2.z + s.w * y2.w;
        o.w = s.x * y3.x + s.y * y3.y + s.z * y3.z + s.w * y3.w;
        op[i * stride] = o;
    }
}

extern "C" void kernel_launch(void* const* d_in, const int* in_sizes, int n_in,
                              void* d_out, int out_size)
{
    const float* in_ = (const float*)d_in[0];   // (4,1,128,272)
    const float* sh  = (const float*)d_in[1];   // (4,128,1,4)
    const float* w   = (const float*)d_in[2];   // (13568,)
    float* out = (float*)d_out;

    tp_stage1<<<NROW, 576>>>(in_, w);
    tp_stage2<<<dim3(34, NN / T1, NB), 256>>>(sh, out);
}